// round 17
// baseline (speedup 1.0000x reference)
#include <cuda_runtime.h>
#include <cstdint>

#define NROWS 50000
#define DIM   128
#define FILT  128
#define RB    20
#define P_EDGES 1600000
#define NTILES (P_EDGES / 64)     // 25000
#define TPB_TILES 10              // tiles per block
#define EDGE_GRID (NTILES / TPB_TILES)  // 2500

// scratch (device globals: no allocation allowed)
__device__ float g_h[NROWS * FILT];
__device__ float g_agg[NROWS * FILT];
__device__ float g_WinT[DIM * FILT];   // [k=d][oc=f]
__device__ float g_WoutT[FILT * DIM];  // [k=f][oc=d]
__device__ int4  g_meta[P_EDGES];      // (idx_i, idx_j, bitcast(rcut), 0)

__device__ __forceinline__ float sspf(float x) {
    // softplus(x) - ln2, fast path. For x>15, log1p(exp(x)) ~= x (err < 3e-7)
    float r = __logf(1.0f + __expf(x));
    r = (x > 15.0f) ? x : r;
    return r - 0.69314718055994530942f;
}

// packed f32x2 helpers
#define PACK2(d, lo, hi) asm("mov.b64 %0, {%1, %2};" : "=l"(d) : "f"(lo), "f"(hi))
#define UNPACK2(lo, hi, s) asm("mov.b64 {%0, %1}, %2;" : "=f"(lo), "=f"(hi) : "l"(s))
#define FMA2(acc, a, b) asm("fma.rn.f32x2 %0, %1, %2, %0;" : "+l"(acc) : "l"(a), "l"(b))

union F4U { float4 f; unsigned long long u[2]; };

// ---------------------------------------------------------------------------
// Fused prelude: weight transposes + meta pack + agg zero in one launch.
// ---------------------------------------------------------------------------
__global__ void prelude_kernel(const float* __restrict__ Win,
                               const float* __restrict__ Wout,
                               const int* __restrict__ idx_i,
                               const int* __restrict__ idx_j,
                               const float* __restrict__ rc) {
    int i = blockIdx.x * blockDim.x + threadIdx.x;
    int stride = gridDim.x * blockDim.x;

    if (i < 128 * 128) {
        int oc = i >> 7, k = i & 127;
        g_WinT[k * 128 + oc]  = Win[oc * 128 + k];
        g_WoutT[k * 128 + oc] = Wout[oc * 128 + k];
    }

    float4 z = make_float4(0.f, 0.f, 0.f, 0.f);
    float4* p = reinterpret_cast<float4*>(g_agg);
    for (int t = i; t < NROWS * FILT / 4; t += stride) p[t] = z;

    for (int t = i; t < P_EDGES; t += stride)
        g_meta[t] = make_int4(idx_i[t], idx_j[t], __float_as_int(rc[t]), 0);
}

// ---------------------------------------------------------------------------
// GEMM with packed-f32x2 mainloop. C[n,oc] = act(sum_k A[n,k]*WT[k,oc]+b[oc])
// A-tile staged DUPLICATED ((a,a) float2 pairs) so one LDS.128 yields two
// packed broadcast multipliers -> zero pack MOVs, FMA-pipe instrs halved.
// Block tile 64x128, thread tile 8x4, K=128.
// ---------------------------------------------------------------------------
template <bool SSP>
__global__ __launch_bounds__(256) void gemm_kernel(const float* __restrict__ A,
                                                   const float* __restrict__ WT,
                                                   const float* __restrict__ bias,
                                                   float* __restrict__ C,
                                                   int nrows) {
    __shared__ float2 Asd[64][32];   // 16 KB, duplicated A values
    __shared__ float  Ws[32][128];   // 16 KB

    int tid  = threadIdx.x;
    int warp = tid >> 5;
    int lane = tid & 31;
    int gr0  = blockIdx.x * 64;
    int r0   = warp * 8;
    int c0   = lane * 4;

    unsigned long long acc01[8], acc23[8];
#pragma unroll
    for (int i = 0; i < 8; i++) { acc01[i] = 0ULL; acc23[i] = 0ULL; }

    for (int k0 = 0; k0 < 128; k0 += 32) {
#pragma unroll
        for (int v = 0; v < 2; v++) {
            int fi  = tid + v * 256;   // 0..511
            int row = fi >> 3;
            int kq  = fi & 7;
            int grow = gr0 + row;
            float4 val = make_float4(0.f, 0.f, 0.f, 0.f);
            if (grow < nrows)
                val = *reinterpret_cast<const float4*>(A + (size_t)grow * 128 + k0 + kq * 4);
            *reinterpret_cast<float4*>(&Asd[row][kq * 4])     = make_float4(val.x, val.x, val.y, val.y);
            *reinterpret_cast<float4*>(&Asd[row][kq * 4 + 2]) = make_float4(val.z, val.z, val.w, val.w);
        }
#pragma unroll
        for (int v = 0; v < 4; v++) {
            int fi = tid + v * 256;    // 0..1023
            int kr = fi >> 5;
            int f4 = fi & 31;
            *reinterpret_cast<float4*>(&Ws[kr][f4 * 4]) =
                *reinterpret_cast<const float4*>(WT + (size_t)(k0 + kr) * 128 + f4 * 4);
        }
        __syncthreads();

#pragma unroll
        for (int kkp = 0; kkp < 16; kkp++) {        // 2 k per iteration
            F4U w0u, w1u;
            w0u.f = *reinterpret_cast<const float4*>(&Ws[2 * kkp][c0]);
            w1u.f = *reinterpret_cast<const float4*>(&Ws[2 * kkp + 1][c0]);
#pragma unroll
            for (int i = 0; i < 8; i++) {
                F4U au;   // (a_e, a_e, a_o, a_o)
                au.f = *reinterpret_cast<const float4*>(&Asd[r0 + i][2 * kkp]);
                FMA2(acc01[i], au.u[0], w0u.u[0]);
                FMA2(acc23[i], au.u[0], w0u.u[1]);
                FMA2(acc01[i], au.u[1], w1u.u[0]);
                FMA2(acc23[i], au.u[1], w1u.u[1]);
            }
        }
        __syncthreads();
    }

    float4 bb = *reinterpret_cast<const float4*>(bias + c0);
#pragma unroll
    for (int i = 0; i < 8; i++) {
        int grow = gr0 + r0 + i;
        if (grow < nrows) {
            float4 o;
            UNPACK2(o.x, o.y, acc01[i]);
            UNPACK2(o.z, o.w, acc23[i]);
            o.x += bb.x; o.y += bb.y; o.z += bb.z; o.w += bb.w;
            if (SSP) {
                o.x = sspf(o.x); o.y = sspf(o.y);
                o.z = sspf(o.z); o.w = sspf(o.w);
            }
            *reinterpret_cast<float4*>(C + (size_t)grow * 128 + c0) = o;
        }
    }
}

// ---------------------------------------------------------------------------
// Edge stage as tiled GEMM, v3 (f32x2 mainloop):
//  - block owns TPB_TILES tiles; Wt/Bs staged once; Fs/Ms register-prefetched
//  - f_ij tile staged DUPLICATED ((a,a) pairs): LDS.128 -> two packed
//    broadcast multipliers, no pack MOVs; FMA-pipe instrs 640 -> 320/thread
//  - bias folded into packed accumulator init
//  - tile loop kept ROLLED (#pragma unroll 1) to bound code size
// Epilogue: ssp(acc)*rcut*h[idx_j] -> red.v4 into agg[idx_i] (coalesced 512B
// rows on L2-resident tables).
// ---------------------------------------------------------------------------
__global__ __launch_bounds__(256) void edge_gemm_kernel(const float* __restrict__ f_ij,
                                                        const float* __restrict__ W_filter,
                                                        const float* __restrict__ b_filter) {
    __shared__ float2 Fsd[64][RB];       // 10 KB duplicated f_ij tile
    __shared__ float  Wt[RB][FILT];      // 10 KB W_filter^T
    __shared__ int4   Ms[64];            // 1 KB  meta tile
    __shared__ float  Bs[FILT];          // 0.5 KB bias

    int tid  = threadIdx.x;
    int warp = tid >> 5;
    int lane = tid & 31;
    int r0   = warp * 8;                 // 8 edge rows per warp
    int c0   = lane * 4;                 // 4 filters per lane

    // stage W^T (transpose on the fly) + bias — once per block
#pragma unroll
    for (int v = 0; v < 10; v++) {
        int idx = tid + v * 256;         // 0..2559
        int f = idx / RB, kk = idx % RB;
        Wt[kk][f] = W_filter[idx];
    }
    if (tid < FILT) Bs[tid] = b_filter[tid];

    int t0 = blockIdx.x * TPB_TILES;

    // stage first tile (duplicated)
    {
        int e0 = t0 * 64;
        if (tid < 64) Ms[tid] = __ldg(&g_meta[e0 + tid]);
        const float* fb = f_ij + (size_t)e0 * RB;
#pragma unroll
        for (int v = 0; v < 5; v++) {
            int idx = tid + v * 256;     // 0..1279
            float fv = __ldg(fb + idx);
            Fsd[idx / RB][idx % RB] = make_float2(fv, fv);
        }
    }
    __syncthreads();

    unsigned long long bb01, bb23;
    PACK2(bb01, Bs[c0],     Bs[c0 + 1]);
    PACK2(bb23, Bs[c0 + 2], Bs[c0 + 3]);

#pragma unroll 1
    for (int t = 0; t < TPB_TILES; t++) {
        // prefetch next tile into registers (hidden under mainloop)
        float pf[5];
        int4  pm;
        if (t + 1 < TPB_TILES) {
            int e1 = (t0 + t + 1) * 64;
            const float* fb = f_ij + (size_t)e1 * RB;
#pragma unroll
            for (int v = 0; v < 5; v++) pf[v] = __ldg(fb + tid + v * 256);
            if (tid < 64) pm = __ldg(&g_meta[e1 + tid]);
        }

        // mainloop: 320 FFMA2 per thread (was 640 FFMA)
        unsigned long long acc01[8], acc23[8];
#pragma unroll
        for (int i = 0; i < 8; i++) { acc01[i] = bb01; acc23[i] = bb23; }

#pragma unroll
        for (int kp = 0; kp < 10; kp++) {
            F4U w0u, w1u;
            w0u.f = *reinterpret_cast<const float4*>(&Wt[2 * kp][c0]);
            w1u.f = *reinterpret_cast<const float4*>(&Wt[2 * kp + 1][c0]);
#pragma unroll
            for (int i = 0; i < 8; i++) {
                F4U au;   // (a_e, a_e, a_o, a_o)
                au.f = *reinterpret_cast<const float4*>(&Fsd[r0 + i][2 * kp]);
                FMA2(acc01[i], au.u[0], w0u.u[0]);
                FMA2(acc23[i], au.u[0], w0u.u[1]);
                FMA2(acc01[i], au.u[1], w1u.u[0]);
                FMA2(acc23[i], au.u[1], w1u.u[1]);
            }
        }

        // epilogue: ssp, cutoff, gather, scatter-add
#pragma unroll
        for (int i = 0; i < 8; i++) {
            int4  mt = Ms[r0 + i];
            float rc = __int_as_float(mt.z);

            float4 hv = *reinterpret_cast<const float4*>(g_h + (size_t)mt.y * FILT + c0);

            float v0, v1, v2, v3;
            UNPACK2(v0, v1, acc01[i]);
            UNPACK2(v2, v3, acc23[i]);

            float ox = sspf(v0) * rc * hv.x;
            float oy = sspf(v1) * rc * hv.y;
            float oz = sspf(v2) * rc * hv.z;
            float ow = sspf(v3) * rc * hv.w;

            float* dst = g_agg + (size_t)mt.x * FILT + c0;
            asm volatile("red.global.add.v4.f32 [%0], {%1, %2, %3, %4};"
                         :: "l"(dst), "f"(ox), "f"(oy), "f"(oz), "f"(ow)
                         : "memory");
        }

        if (t + 1 < TPB_TILES) {
            __syncthreads();   // all reads of current tile done
#pragma unroll
            for (int v = 0; v < 5; v++) {
                int idx = tid + v * 256;
                Fsd[idx / RB][idx % RB] = make_float2(pf[v], pf[v]);
            }
            if (tid < 64) Ms[tid] = pm;
            __syncthreads();   // next tile visible
        }
    }
}

// ---------------------------------------------------------------------------
extern "C" void kernel_launch(void* const* d_in, const int* in_sizes, int n_in,
                              void* d_out, int out_size) {
    int ix = -1, ifij = -1, iwf = -1;
    int i16k[4]; int n16k = 0;       // W_in, W_out (16384 elems each)
    int i1m6[4]; int n1m6 = 0;       // idx_i, idx_j, rcut_ij (1.6M each)
    int i128[4]; int n128 = 0;       // b_in, b_filter, b_out (128 each)

    for (int i = 0; i < n_in; i++) {
        long s = in_sizes[i];
        if      (s == 6400000)  ix   = i;              // x [1,50000,128]
        else if (s == 32000000) ifij = i;              // f_ij [P,20]
        else if (s == 2560)     iwf  = i;              // W_filter [128,20]
        else if (s == 16384)  { if (n16k < 4) i16k[n16k++] = i; }
        else if (s == 1600000){ if (n1m6 < 4) i1m6[n1m6++] = i; }
        else if (s == 128)    { if (n128 < 4) i128[n128++] = i; }
    }

    const float* x        = (const float*)d_in[ix];
    const float* f_ij     = (const float*)d_in[ifij];
    const float* W_filter = (const float*)d_in[iwf];
    const int*   idx_i    = (const int*)d_in[i1m6[0]];
    const int*   idx_j    = (const int*)d_in[i1m6[1]];
    const float* rcut_ij  = (const float*)d_in[i1m6[2]];
    const float* W_in     = (const float*)d_in[i16k[0]];
    const float* W_out    = (const float*)d_in[i16k[1]];
    bool sorted_keys = (i128[0] < ifij);
    const float* b_in     = (const float*)d_in[sorted_keys ? i128[1] : i128[0]];
    const float* b_filter = (const float*)d_in[sorted_keys ? i128[0] : i128[1]];
    const float* b_out    = (const float*)d_in[i128[2]];

    float* out = (float*)d_out;

    // Resolve REAL device addresses of scratch globals (host query, no alloc,
    // executes immediately — safe under graph capture).
    void *p_h, *p_agg, *p_WinT, *p_WoutT;
    cudaGetSymbolAddress(&p_h,     g_h);
    cudaGetSymbolAddress(&p_agg,   g_agg);
    cudaGetSymbolAddress(&p_WinT,  g_WinT);
    cudaGetSymbolAddress(&p_WoutT, g_WoutT);
    float* dev_h     = (float*)p_h;
    float* dev_agg   = (float*)p_agg;
    float* dev_WinT  = (float*)p_WinT;
    float* dev_WoutT = (float*)p_WoutT;

    // 1. fused prelude: transposes + meta pack + agg zero
    prelude_kernel<<<2048, 256>>>(W_in, W_out, idx_i, idx_j, rcut_ij);

    // 2. h = x @ W_in^T + b_in
    gemm_kernel<false><<<(NROWS + 63) / 64, 256>>>(x, dev_WinT, b_in, dev_h, NROWS);

    // 3. edge stage as tiled GEMM + fused epilogue (gather/ssp/scatter)
    edge_gemm_kernel<<<EDGE_GRID, 256>>>(f_ij, W_filter, b_filter);

    // 4. out = ssp(agg @ W_out^T + b_out)
    gemm_kernel<true><<<(NROWS + 63) / 64, 256>>>(dev_agg, dev_WoutT, b_out, out, NROWS);
}